// round 6
// baseline (speedup 1.0000x reference)
#include <cuda_runtime.h>
#include <cstdint>

// ---------------- problem constants ----------------
#define TT 50176
#define DD 1024
#define EE 2048
#define NS 8
#define EPS 1e-5f

#define NBLK 392            // token blocks of 128
#define NET 16              // e tiles of 128
#define NKC 32              // K chunks of 32
#define NCH (NET * NKC)     // 512 chunks
#define CH 4096             // floats per packed 128x32 chunk
#define STG 3
#define SMEM_FLOATS (STG * 8192 + 1024)     // 25600 fl = 102400 B

// ---------------- scratch (device globals; no allocation) ----------------
__device__ float g_xnt[(size_t)NBLK * NKC * CH];  // frag-packed xn (tf32)
__device__ float g_wpt[(size_t)NET * NKC * CH];   // frag-packed Wp (tf32), nf pair-packed

// ---------------- helpers ----------------
__device__ __forceinline__ float tf32_rna(float v) {
    uint32_t u; asm("cvt.rna.tf32.f32 %0, %1;" : "=r"(u) : "f"(v));
    return __uint_as_float(u);
}
__device__ __forceinline__ float silu_f(float v) { return v * (1.0f / (1.0f + __expf(-v))); }
__device__ __forceinline__ uint32_t smem_u32(const void* p) {
    uint32_t a;
    asm("{ .reg .u64 t; cvta.to.shared.u64 t, %1; cvt.u32.u64 %0, t; }" : "=r"(a) : "l"(p));
    return a;
}
#define CP_ASYNC16(dst, src) \
    asm volatile("cp.async.cg.shared.global [%0], [%1], 16;" :: "r"(dst), "l"(src))
#define CP_COMMIT() asm volatile("cp.async.commit_group;")
#define CP_WAIT(n)  asm volatile("cp.async.wait_group %0;" :: "n"(n))

__device__ __forceinline__ void mma_tf32(float d[4], const uint32_t a[4],
                                         uint32_t b0, uint32_t b1) {
    asm volatile(
        "mma.sync.aligned.m16n8k8.row.col.f32.tf32.tf32.f32 "
        "{%0,%1,%2,%3}, {%4,%5,%6,%7}, {%8,%9}, {%0,%1,%2,%3};"
        : "+f"(d[0]), "+f"(d[1]), "+f"(d[2]), "+f"(d[3])
        : "r"(a[0]), "r"(a[1]), "r"(a[2]), "r"(a[3]), "r"(b0), "r"(b1));
}

// ---------------- kernel 1: LN + tf32 round + fragment packing (BK=32 chunks) ----------
__global__ void __launch_bounds__(256)
prep(const float* __restrict__ x, const float* __restrict__ Wp,
     const float* __restrict__ gamma, const float* __restrict__ beta)
{
    __shared__ float s_mu[128], s_rstd[128];
    __shared__ float s_t[128 * 36];
    const int bid = blockIdx.x, tid = threadIdx.x;
    const bool isW = (bid >= NBLK);
    const float* src = isW ? Wp + (size_t)(bid - NBLK) * 128 * DD
                           : x + (size_t)bid * 128 * DD;
    float* dst = isW ? g_wpt + (size_t)(bid - NBLK) * NKC * CH
                     : g_xnt + (size_t)bid * NKC * CH;

    if (!isW) {
        int tk = tid >> 1, half = tid & 1;
        const float4* xr = reinterpret_cast<const float4*>(src + (size_t)tk * DD + half * (DD / 2));
        float s = 0.f, ss = 0.f;
#pragma unroll 4
        for (int i = 0; i < DD / 8; i++) {
            float4 v = xr[i];
            s  += v.x + v.y + v.z + v.w;
            ss += v.x * v.x + v.y * v.y + v.z * v.z + v.w * v.w;
        }
        s  += __shfl_xor_sync(0xFFFFFFFFu, s, 1);
        ss += __shfl_xor_sync(0xFFFFFFFFu, ss, 1);
        if (!half) {
            float mu = s * (1.0f / DD);
            float var = ss * (1.0f / DD) - mu * mu;
            s_mu[tk] = mu; s_rstd[tk] = rsqrtf(var + EPS);
        }
    }
    __syncthreads();

    for (int kc = 0; kc < NKC; kc++) {
#pragma unroll
        for (int i = 0; i < 4; i++) {
            int id = i * 256 + tid;          // 1024 float4s = 128 rows x 8
            int row = id >> 3, c4 = id & 7;
            float4 v = *reinterpret_cast<const float4*>(src + (size_t)row * DD + kc * 32 + c4 * 4);
            *reinterpret_cast<float4*>(s_t + row * 36 + c4 * 4) = v;
        }
        __syncthreads();
        if (isW) {
#pragma unroll
            for (int j = 0; j < 16; j++) {
                int o = j * 256 + tid;
                int MS = o >> 7, NFP = MS >> 2, ks = MS & 3;
                int l = (o >> 2) & 31, g = l >> 2, t = l & 3, jj = o & 3;
                int n = NFP * 16 + (jj >> 1) * 8 + g, kk = ks * 8 + (jj & 1) * 4 + t;
                dst[(size_t)kc * CH + o] = tf32_rna(s_t[n * 36 + kk]);
            }
        } else {
#pragma unroll
            for (int j = 0; j < 16; j++) {
                int o = j * 256 + tid;
                int MS = o >> 7, MF = MS >> 2, ks = MS & 3;
                int l = (o >> 2) & 31, g = l >> 2, r = l & 3;
                int ri = o & 3, q = ri >> 1, hi = ri & 1;
                int m = MF * 16 + hi * 8 + g, kk = ks * 8 + q * 4 + r;
                int k = kc * 32 + kk;
                float v = s_t[m * 36 + kk];
                v = fmaf((v - s_mu[m]) * s_rstd[m], gamma[k], beta[k]);
                dst[(size_t)kc * CH + o] = tf32_rna(v);
            }
        }
        __syncthreads();
    }
}

// ---------------- kernel 2: mma.sync GEMM (8 warps, 64x32 tiles, pipelined) ----------
__global__ void __launch_bounds__(256, 2)
mamba_mma(const float* __restrict__ x,   const float* __restrict__ bp,
          const float* __restrict__ Wst, const float* __restrict__ bst,
          const float* __restrict__ Wo,  const float* __restrict__ bo,
          const float* __restrict__ istate, float* __restrict__ out)
{
    extern __shared__ float sm[];
    float* s_su = sm + STG * 8192;           // [128][8]
    const int tid = threadIdx.x, lane = tid & 31, wid = tid >> 5;
    const int wm = wid >> 2, wn = wid & 3;   // 2x4 warp grid, 64x32 per warp
    const int tb = blockIdx.x;
    const uint32_t sb = smem_u32(sm);
    const int g = lane >> 2, t = lane & 3;

    for (int i = tid; i < 1024; i += 256) s_su[i] = 0.f;

    const float* Ab = g_xnt + (size_t)tb * NKC * CH;

    auto stage = [&](int c) {
        int st = c % 3, et = c >> 5, kc = c & 31;
        const float* As = Ab + (size_t)kc * CH;
        const float* Bs = g_wpt + ((size_t)et * NKC + kc) * CH;
        uint32_t d = sb + st * 32768;
#pragma unroll
        for (int i = 0; i < 4; i++) {
            int id = i * 256 + tid;
            CP_ASYNC16(d + id * 16, As + id * 4);
            CP_ASYNC16(d + 16384 + id * 16, Bs + id * 4);
        }
        CP_COMMIT();
    };
    stage(0); stage(1);

    float acc[4][4][4];
#pragma unroll
    for (int mf = 0; mf < 4; mf++)
#pragma unroll
        for (int nf = 0; nf < 4; nf++)
#pragma unroll
            for (int r = 0; r < 4; r++) acc[mf][nf][r] = 0.f;

    const int aoff = wm * 2048 + lane * 4;   // (wm*4+mf)*4+ks)*128 : mf*16*... precomputed below
    const int boff = wn * 1024 + lane * 4;

    for (int c = 0; c < NCH; c++) {
        CP_WAIT(1);
        __syncthreads();
        if (c + 2 < NCH) stage(c + 2);

        const float* As = sm + (c % 3) * 8192;
        const float* Bs = As + 4096;

        // explicit software pipeline over ks with double-buffered fragments
        uint32_t a[2][4][4], b[2][2][4];

#define LD_FRAGS(ks, buf)                                                          \
        do {                                                                       \
            _Pragma("unroll")                                                      \
            for (int mf = 0; mf < 4; mf++) {                                       \
                float4 v = *reinterpret_cast<const float4*>(                       \
                    As + aoff + (mf * 4 + (ks)) * 128);                            \
                a[buf][mf][0] = __float_as_uint(v.x);                              \
                a[buf][mf][1] = __float_as_uint(v.y);                              \
                a[buf][mf][2] = __float_as_uint(v.z);                              \
                a[buf][mf][3] = __float_as_uint(v.w);                              \
            }                                                                      \
            _Pragma("unroll")                                                      \
            for (int p = 0; p < 2; p++) {                                          \
                float4 v = *reinterpret_cast<const float4*>(                       \
                    Bs + boff + (p * 4 + (ks)) * 128);                             \
                b[buf][p][0] = __float_as_uint(v.x);                               \
                b[buf][p][1] = __float_as_uint(v.y);                               \
                b[buf][p][2] = __float_as_uint(v.z);                               \
                b[buf][p][3] = __float_as_uint(v.w);                               \
            }                                                                      \
        } while (0)

        LD_FRAGS(0, 0);
#pragma unroll
        for (int ks = 0; ks < 4; ks++) {
            const int cur = ks & 1, nxt = cur ^ 1;
            if (ks < 3) LD_FRAGS(ks + 1, nxt);
#pragma unroll
            for (int mf = 0; mf < 4; mf++)
#pragma unroll
                for (int p = 0; p < 2; p++) {
                    mma_tf32(acc[mf][p * 2],     a[cur][mf], b[cur][p][0], b[cur][p][1]);
                    mma_tf32(acc[mf][p * 2 + 1], a[cur][mf], b[cur][p][2], b[cur][p][3]);
                }
        }
#undef LD_FRAGS

        if ((c & 31) == 31) {
            const int et = c >> 5;
#pragma unroll
            for (int mf = 0; mf < 4; mf++) {
                float pr0[8], pr1[8];
#pragma unroll
                for (int n = 0; n < 8; n++) { pr0[n] = 0.f; pr1[n] = 0.f; }
#pragma unroll
                for (int nf = 0; nf < 4; nf++) {
                    int col0 = et * 128 + wn * 32 + nf * 8 + 2 * t;
                    float bp0 = bp[col0], bp1 = bp[col0 + 1];
                    float s00 = silu_f(acc[mf][nf][0] + bp0);
                    float s01 = silu_f(acc[mf][nf][1] + bp1);
                    float s10 = silu_f(acc[mf][nf][2] + bp0);
                    float s11 = silu_f(acc[mf][nf][3] + bp1);
#pragma unroll
                    for (int n = 0; n < 8; n++) {
                        float w0 = Wst[n * EE + col0], w1 = Wst[n * EE + col0 + 1];
                        pr0[n] = fmaf(s00, w0, fmaf(s01, w1, pr0[n]));
                        pr1[n] = fmaf(s10, w0, fmaf(s11, w1, pr1[n]));
                    }
                }
#pragma unroll
                for (int n = 0; n < 8; n++) {
                    pr0[n] += __shfl_xor_sync(0xFFFFFFFFu, pr0[n], 1);
                    pr0[n] += __shfl_xor_sync(0xFFFFFFFFu, pr0[n], 2);
                    pr1[n] += __shfl_xor_sync(0xFFFFFFFFu, pr1[n], 1);
                    pr1[n] += __shfl_xor_sync(0xFFFFFFFFu, pr1[n], 2);
                }
                if (t == 0) {
                    int r0 = wm * 64 + mf * 16 + g;
#pragma unroll
                    for (int n = 0; n < 8; n++) {
                        atomicAdd(&s_su[r0 * 8 + n], pr0[n]);
                        atomicAdd(&s_su[(r0 + 8) * 8 + n], pr1[n]);
                    }
                }
            }
#pragma unroll
            for (int mf = 0; mf < 4; mf++)
#pragma unroll
                for (int nf = 0; nf < 4; nf++)
#pragma unroll
                    for (int r = 0; r < 4; r++) acc[mf][nf][r] = 0.f;
        }
    }
    __syncthreads();

    // current_state = silu(init + b_state + su)
    for (int i = tid; i < 1024; i += 256) {
        int n = i & 7;
        s_su[i] = silu_f(s_su[i] + bst[n] + istate[n]);
    }
    __syncthreads();

    // tail: out = x + cs @ WoT + bo
    const float4* x4 = reinterpret_cast<const float4*>(x + (size_t)tb * 128 * DD);
    float4*       o4 = reinterpret_cast<float4*>(out + (size_t)tb * 128 * DD);
    for (int idx = tid; idx < 128 * (DD / 4); idx += 256) {
        int tt = idx >> 8, cc = idx & 255;
        float4 xv  = x4[idx];
        float4 cs0 = *reinterpret_cast<const float4*>(s_su + tt * NS);
        float4 cs1 = *reinterpret_cast<const float4*>(s_su + tt * NS + 4);
        float xin[4] = {xv.x, xv.y, xv.z, xv.w};
        float ov[4];
        int d0 = cc * 4;
#pragma unroll
        for (int dd = 0; dd < 4; dd++) {
            int d = d0 + dd;
            const float4* wo = reinterpret_cast<const float4*>(Wo + (size_t)d * NS);
            float4 w0 = wo[0], w1 = wo[1];
            float o = bo[d];
            o = fmaf(cs0.x, w0.x, o); o = fmaf(cs0.y, w0.y, o);
            o = fmaf(cs0.z, w0.z, o); o = fmaf(cs0.w, w0.w, o);
            o = fmaf(cs1.x, w1.x, o); o = fmaf(cs1.y, w1.y, o);
            o = fmaf(cs1.z, w1.z, o); o = fmaf(cs1.w, w1.w, o);
            ov[dd] = xin[dd] + o;
        }
        o4[idx] = make_float4(ov[0], ov[1], ov[2], ov[3]);
    }
}

extern "C" void kernel_launch(void* const* d_in, const int* in_sizes, int n_in,
                              void* d_out, int out_size) {
    (void)in_sizes; (void)n_in; (void)out_size;
    const float* x      = (const float*)d_in[0];
    const float* Wp     = (const float*)d_in[1];
    const float* bp     = (const float*)d_in[2];
    const float* Wst    = (const float*)d_in[3];
    const float* bst    = (const float*)d_in[4];
    const float* Wo     = (const float*)d_in[5];
    const float* bo     = (const float*)d_in[6];
    const float* istate = (const float*)d_in[7];
    const float* gamma  = (const float*)d_in[8];
    const float* beta   = (const float*)d_in[9];

    prep<<<NBLK + NET, 256>>>(x, Wp, gamma, beta);

    cudaFuncSetAttribute(mamba_mma,
                         cudaFuncAttributeMaxDynamicSharedMemorySize, SMEM_FLOATS * 4);
    mamba_mma<<<NBLK, 256, SMEM_FLOATS * 4>>>(x, bp, Wst, bst, Wo, bo, istate, (float*)d_out);
}

// round 7
// speedup vs baseline: 1.0482x; 1.0482x over previous
#include <cuda_runtime.h>
#include <cstdint>

// ---------------- problem constants ----------------
#define TT 50176
#define DD 1024
#define EE 2048
#define NS 8
#define EPS 1e-5f

#define NBLK 392            // token blocks of 128
#define NET 16              // packed e chunks of 128 cols
#define NKC 32              // K chunks of 32
#define CH 4096             // floats per packed 128x32 chunk
#define NCH 256             // 8 et-passes (N=256) x 32 kc
#define STG 3
#define STAGE_FL 12288      // A 4096 + B 8192 floats
#define SMEM_FLOATS (STG * STAGE_FL + 1024)   // 37888 fl = 151552 B

// ---------------- scratch (device globals; no allocation) ----------------
__device__ float g_xnt[(size_t)NBLK * NKC * CH];  // frag-packed xn (tf32)
__device__ float g_wpt[(size_t)NET * NKC * CH];   // frag-packed Wp (tf32), nf pair-packed

// ---------------- helpers ----------------
__device__ __forceinline__ float tf32_rna(float v) {
    uint32_t u; asm("cvt.rna.tf32.f32 %0, %1;" : "=r"(u) : "f"(v));
    return __uint_as_float(u);
}
__device__ __forceinline__ float silu_f(float v) { return v * (1.0f / (1.0f + __expf(-v))); }
__device__ __forceinline__ uint32_t smem_u32(const void* p) {
    uint32_t a;
    asm("{ .reg .u64 t; cvta.to.shared.u64 t, %1; cvt.u32.u64 %0, t; }" : "=r"(a) : "l"(p));
    return a;
}
#define CP_ASYNC16(dst, src) \
    asm volatile("cp.async.cg.shared.global [%0], [%1], 16;" :: "r"(dst), "l"(src))
#define CP_COMMIT() asm volatile("cp.async.commit_group;")
#define CP_WAIT(n)  asm volatile("cp.async.wait_group %0;" :: "n"(n))

__device__ __forceinline__ void mma_tf32(float d[4], const uint32_t a[4],
                                         uint32_t b0, uint32_t b1) {
    asm volatile(
        "mma.sync.aligned.m16n8k8.row.col.f32.tf32.tf32.f32 "
        "{%0,%1,%2,%3}, {%4,%5,%6,%7}, {%8,%9}, {%0,%1,%2,%3};"
        : "+f"(d[0]), "+f"(d[1]), "+f"(d[2]), "+f"(d[3])
        : "r"(a[0]), "r"(a[1]), "r"(a[2]), "r"(a[3]), "r"(b0), "r"(b1));
}

// ---------------- kernel 1: LN + tf32 round + fragment packing (BK=32 chunks) ----------
__global__ void __launch_bounds__(256)
prep(const float* __restrict__ x, const float* __restrict__ Wp,
     const float* __restrict__ gamma, const float* __restrict__ beta)
{
    __shared__ float s_mu[128], s_rstd[128];
    __shared__ float s_t[128 * 36];
    const int bid = blockIdx.x, tid = threadIdx.x;
    const bool isW = (bid >= NBLK);
    const float* src = isW ? Wp + (size_t)(bid - NBLK) * 128 * DD
                           : x + (size_t)bid * 128 * DD;
    float* dst = isW ? g_wpt + (size_t)(bid - NBLK) * NKC * CH
                     : g_xnt + (size_t)bid * NKC * CH;

    if (!isW) {
        int tk = tid >> 1, half = tid & 1;
        const float4* xr = reinterpret_cast<const float4*>(src + (size_t)tk * DD + half * (DD / 2));
        float s = 0.f, ss = 0.f;
#pragma unroll 4
        for (int i = 0; i < DD / 8; i++) {
            float4 v = xr[i];
            s  += v.x + v.y + v.z + v.w;
            ss += v.x * v.x + v.y * v.y + v.z * v.z + v.w * v.w;
        }
        s  += __shfl_xor_sync(0xFFFFFFFFu, s, 1);
        ss += __shfl_xor_sync(0xFFFFFFFFu, ss, 1);
        if (!half) {
            float mu = s * (1.0f / DD);
            float var = ss * (1.0f / DD) - mu * mu;
            s_mu[tk] = mu; s_rstd[tk] = rsqrtf(var + EPS);
        }
    }
    __syncthreads();

    for (int kc = 0; kc < NKC; kc++) {
#pragma unroll
        for (int i = 0; i < 4; i++) {
            int id = i * 256 + tid;
            int row = id >> 3, c4 = id & 7;
            float4 v = *reinterpret_cast<const float4*>(src + (size_t)row * DD + kc * 32 + c4 * 4);
            *reinterpret_cast<float4*>(s_t + row * 36 + c4 * 4) = v;
        }
        __syncthreads();
        if (isW) {
#pragma unroll
            for (int j = 0; j < 16; j++) {
                int o = j * 256 + tid;
                int MS = o >> 7, NFP = MS >> 2, ks = MS & 3;
                int l = (o >> 2) & 31, g = l >> 2, t = l & 3, jj = o & 3;
                int n = NFP * 16 + (jj >> 1) * 8 + g, kk = ks * 8 + (jj & 1) * 4 + t;
                dst[(size_t)kc * CH + o] = tf32_rna(s_t[n * 36 + kk]);
            }
        } else {
#pragma unroll
            for (int j = 0; j < 16; j++) {
                int o = j * 256 + tid;
                int MS = o >> 7, MF = MS >> 2, ks = MS & 3;
                int l = (o >> 2) & 31, g = l >> 2, r = l & 3;
                int ri = o & 3, q = ri >> 1, hi = ri & 1;
                int m = MF * 16 + hi * 8 + g, kk = ks * 8 + q * 4 + r;
                int k = kc * 32 + kk;
                float v = s_t[m * 36 + kk];
                v = fmaf((v - s_mu[m]) * s_rstd[m], gamma[k], beta[k]);
                dst[(size_t)kc * CH + o] = tf32_rna(v);
            }
        }
        __syncthreads();
    }
}

// ---------------- kernel 2: mma.sync GEMM (8 warps, 64x64 tiles, CTA 128x256) --------
__global__ void __launch_bounds__(256, 1)
mamba_mma(const float* __restrict__ x,   const float* __restrict__ bp,
          const float* __restrict__ Wst, const float* __restrict__ bst,
          const float* __restrict__ Wo,  const float* __restrict__ bo,
          const float* __restrict__ istate, float* __restrict__ out)
{
    extern __shared__ float sm[];
    float* s_su = sm + STG * STAGE_FL;       // [128][8]
    const int tid = threadIdx.x, lane = tid & 31, wid = tid >> 5;
    const int wm = wid >> 2, wn = wid & 3;   // 2x4 warp grid, 64x64 per warp
    const int tb = blockIdx.x;
    const uint32_t sb = smem_u32(sm);
    const int g = lane >> 2, t = lane & 3;

    for (int i = tid; i < 1024; i += 256) s_su[i] = 0.f;

    const float* Ab = g_xnt + (size_t)tb * NKC * CH;

    auto stage = [&](int c) {
        int st = c % 3, et = c >> 5, kc = c & 31;
        const float* As  = Ab + (size_t)kc * CH;
        const float* B0  = g_wpt + ((size_t)(et * 2) * NKC + kc) * CH;
        const float* B1  = g_wpt + ((size_t)(et * 2 + 1) * NKC + kc) * CH;
        uint32_t d = sb + st * (STAGE_FL * 4);
#pragma unroll
        for (int i = 0; i < 4; i++) {
            int id = i * 256 + tid;
            CP_ASYNC16(d + id * 16, As + id * 4);
            CP_ASYNC16(d + 16384 + id * 16, B0 + id * 4);
            CP_ASYNC16(d + 32768 + id * 16, B1 + id * 4);
        }
        CP_COMMIT();
    };
    stage(0); stage(1);

    float acc[4][8][4];
#pragma unroll
    for (int mf = 0; mf < 4; mf++)
#pragma unroll
        for (int nf = 0; nf < 8; nf++)
#pragma unroll
            for (int r = 0; r < 4; r++) acc[mf][nf][r] = 0.f;

    const int aoff = wm * 2048 + lane * 4;                        // A: (wm*4+mf, ks)
    const int boff = (wn >> 1) * 4096 + (wn & 1) * 2048 + lane * 4; // B: warp's 64 cols

    for (int c = 0; c < NCH; c++) {
        CP_WAIT(1);
        __syncthreads();
        if (c + 2 < NCH) stage(c + 2);

        const float* As = sm + (c % 3) * STAGE_FL;
        const float* Bs = As + 4096 + boff;
#pragma unroll
        for (int ks = 0; ks < 4; ks++) {
            uint32_t a[4][4], b[4][4];
#pragma unroll
            for (int mf = 0; mf < 4; mf++) {
                float4 v = *reinterpret_cast<const float4*>(
                    As + aoff + (mf * 4 + ks) * 128);
                a[mf][0] = __float_as_uint(v.x); a[mf][1] = __float_as_uint(v.y);
                a[mf][2] = __float_as_uint(v.z); a[mf][3] = __float_as_uint(v.w);
            }
#pragma unroll
            for (int p = 0; p < 4; p++) {
                float4 v = *reinterpret_cast<const float4*>(
                    Bs + (p * 4 + ks) * 128);
                b[p][0] = __float_as_uint(v.x); b[p][1] = __float_as_uint(v.y);
                b[p][2] = __float_as_uint(v.z); b[p][3] = __float_as_uint(v.w);
            }
#pragma unroll
            for (int mf = 0; mf < 4; mf++)
#pragma unroll
                for (int p = 0; p < 4; p++) {
                    mma_tf32(acc[mf][p * 2],     a[mf], b[p][0], b[p][1]);
                    mma_tf32(acc[mf][p * 2 + 1], a[mf], b[p][2], b[p][3]);
                }
        }

        if ((c & 31) == 31) {
            const int et = c >> 5;
#pragma unroll
            for (int mf = 0; mf < 4; mf++) {
                float pr0[8], pr1[8];
#pragma unroll
                for (int n = 0; n < 8; n++) { pr0[n] = 0.f; pr1[n] = 0.f; }
#pragma unroll
                for (int nf = 0; nf < 8; nf++) {
                    int col0 = et * 256 + wn * 64 + nf * 8 + 2 * t;
                    float bp0 = bp[col0], bp1 = bp[col0 + 1];
                    float s00 = silu_f(acc[mf][nf][0] + bp0);
                    float s01 = silu_f(acc[mf][nf][1] + bp1);
                    float s10 = silu_f(acc[mf][nf][2] + bp0);
                    float s11 = silu_f(acc[mf][nf][3] + bp1);
#pragma unroll
                    for (int n = 0; n < 8; n++) {
                        float w0 = Wst[n * EE + col0], w1 = Wst[n * EE + col0 + 1];
                        pr0[n] = fmaf(s00, w0, fmaf(s01, w1, pr0[n]));
                        pr1[n] = fmaf(s10, w0, fmaf(s11, w1, pr1[n]));
                    }
                }
#pragma unroll
                for (int n = 0; n < 8; n++) {
                    pr0[n] += __shfl_xor_sync(0xFFFFFFFFu, pr0[n], 1);
                    pr0[n] += __shfl_xor_sync(0xFFFFFFFFu, pr0[n], 2);
                    pr1[n] += __shfl_xor_sync(0xFFFFFFFFu, pr1[n], 1);
                    pr1[n] += __shfl_xor_sync(0xFFFFFFFFu, pr1[n], 2);
                }
                if (t == 0) {
                    int r0 = wm * 64 + mf * 16 + g;
#pragma unroll
                    for (int n = 0; n < 8; n++) {
                        atomicAdd(&s_su[r0 * 8 + n], pr0[n]);
                        atomicAdd(&s_su[(r0 + 8) * 8 + n], pr1[n]);
                    }
                }
            }
#pragma unroll
            for (int mf = 0; mf < 4; mf++)
#pragma unroll
                for (int nf = 0; nf < 8; nf++)
#pragma unroll
                    for (int r = 0; r < 4; r++) acc[mf][nf][r] = 0.f;
        }
    }
    __syncthreads();

    // current_state = silu(init + b_state + su)
    for (int i = tid; i < 1024; i += 256) {
        int n = i & 7;
        s_su[i] = silu_f(s_su[i] + bst[n] + istate[n]);
    }
    __syncthreads();

    // tail: out = x + cs @ WoT + bo
    const float4* x4 = reinterpret_cast<const float4*>(x + (size_t)tb * 128 * DD);
    float4*       o4 = reinterpret_cast<float4*>(out + (size_t)tb * 128 * DD);
    for (int idx = tid; idx < 128 * (DD / 4); idx += 256) {
        int tt = idx >> 8, cc = idx & 255;
        float4 xv  = x4[idx];
        float4 cs0 = *reinterpret_cast<const float4*>(s_su + tt * NS);
        float4 cs1 = *reinterpret_cast<const float4*>(s_su + tt * NS + 4);
        float xin[4] = {xv.x, xv.y, xv.z, xv.w};
        float ov[4];
        int d0 = cc * 4;
#pragma unroll
        for (int dd = 0; dd < 4; dd++) {
            int d = d0 + dd;
            const float4* wo = reinterpret_cast<const float4*>(Wo + (size_t)d * NS);
            float4 w0 = wo[0], w1 = wo[1];
            float o = bo[d];
            o = fmaf(cs0.x, w0.x, o); o = fmaf(cs0.y, w0.y, o);
            o = fmaf(cs0.z, w0.z, o); o = fmaf(cs0.w, w0.w, o);
            o = fmaf(cs1.x, w1.x, o); o = fmaf(cs1.y, w1.y, o);
            o = fmaf(cs1.z, w1.z, o); o = fmaf(cs1.w, w1.w, o);
            ov[dd] = xin[dd] + o;
        }
        o4[idx] = make_float4(ov[0], ov[1], ov[2], ov[3]);
    }
}

extern "C" void kernel_launch(void* const* d_in, const int* in_sizes, int n_in,
                              void* d_out, int out_size) {
    (void)in_sizes; (void)n_in; (void)out_size;
    const float* x      = (const float*)d_in[0];
    const float* Wp     = (const float*)d_in[1];
    const float* bp     = (const float*)d_in[2];
    const float* Wst    = (const float*)d_in[3];
    const float* bst    = (const float*)d_in[4];
    const float* Wo     = (const float*)d_in[5];
    const float* bo     = (const float*)d_in[6];
    const float* istate = (const float*)d_in[7];
    const float* gamma  = (const float*)d_in[8];
    const float* beta   = (const float*)d_in[9];

    prep<<<NBLK + NET, 256>>>(x, Wp, gamma, beta);

    cudaFuncSetAttribute(mamba_mma,
                         cudaFuncAttributeMaxDynamicSharedMemorySize, SMEM_FLOATS * 4);
    mamba_mma<<<NBLK, 256, SMEM_FLOATS * 4>>>(x, bp, Wst, bst, Wo, bo, istate, (float*)d_out);
}

// round 8
// speedup vs baseline: 1.4245x; 1.3590x over previous
#include <cuda_runtime.h>
#include <cuda_fp16.h>
#include <cstdint>

// ---------------- problem constants ----------------
#define TT 50176
#define DD 1024
#define EE 2048
#define NS 8
#define EPS 1e-5f

#define NBLK 392            // token blocks of 128
#define NET 16              // packed e chunks of 128 cols
#define NKC 32              // K chunks of 32
#define CHU 2048            // u32 (half2) per packed 128x32 chunk
#define NCH 256             // 8 et-passes (N=256) x 32 kc
#define STG 3
#define STAGE_U32 6144      // A 2048 + B 2x2048
#define SMEM_BYTES (STG * STAGE_U32 * 4 + 4096)   // 77824

// ---------------- scratch (device globals; no allocation) ----------------
__device__ uint32_t g_xnt[(size_t)NBLK * NKC * CHU];  // frag-packed xn (fp16)
__device__ uint32_t g_wpt[(size_t)NET * NKC * CHU];   // frag-packed Wp (fp16)

// ---------------- helpers ----------------
__device__ __forceinline__ float silu_f(float v) { return v * (1.0f / (1.0f + __expf(-v))); }
__device__ __forceinline__ uint32_t smem_u32(const void* p) {
    uint32_t a;
    asm("{ .reg .u64 t; cvta.to.shared.u64 t, %1; cvt.u32.u64 %0, t; }" : "=r"(a) : "l"(p));
    return a;
}
__device__ __forceinline__ uint32_t pack_h2(float lo, float hi) {
    __half2 h = __halves2half2(__float2half_rn(lo), __float2half_rn(hi));
    return *reinterpret_cast<uint32_t*>(&h);
}
#define CP_ASYNC16(dst, src) \
    asm volatile("cp.async.cg.shared.global [%0], [%1], 16;" :: "r"(dst), "l"(src))
#define CP_COMMIT() asm volatile("cp.async.commit_group;")
#define CP_WAIT(n)  asm volatile("cp.async.wait_group %0;" :: "n"(n))

__device__ __forceinline__ void mma_f16(float d[4], const uint32_t a[4],
                                        uint32_t b0, uint32_t b1) {
    asm volatile(
        "mma.sync.aligned.m16n8k16.row.col.f32.f16.f16.f32 "
        "{%0,%1,%2,%3}, {%4,%5,%6,%7}, {%8,%9}, {%0,%1,%2,%3};"
        : "+f"(d[0]), "+f"(d[1]), "+f"(d[2]), "+f"(d[3])
        : "r"(a[0]), "r"(a[1]), "r"(a[2]), "r"(a[3]), "r"(b0), "r"(b1));
}

// ---------------- kernel 1: LN + fp16 round + fragment packing (K32 chunks) ----------
// A chunk (2048 u32): o = (MF*2+ks)*128 + lane*4 + r  (MF 0..7, ks 0..1)
//   m = MF*16 + (r&1)*8 + g ; k0 = ks*16 + (r>>1)*8 + 2t ; u32 = {h(k0), h(k0+1)}
// B chunk (2048 u32): o = (NFP*2+ks)*128 + lane*4 + j  (NFP 0..7)
//   n = NFP*16 + (j>>1)*8 + g ; k0 = ks*16 + (j&1)*8 + 2t
__global__ void __launch_bounds__(256)
prep(const float* __restrict__ x, const float* __restrict__ Wp,
     const float* __restrict__ gamma, const float* __restrict__ beta)
{
    __shared__ float s_mu[128], s_rstd[128];
    __shared__ float s_t[128 * 36];
    const int bid = blockIdx.x, tid = threadIdx.x;
    const bool isW = (bid >= NBLK);
    const float* src = isW ? Wp + (size_t)(bid - NBLK) * 128 * DD
                           : x + (size_t)bid * 128 * DD;
    uint32_t* dst = isW ? g_wpt + (size_t)(bid - NBLK) * NKC * CHU
                        : g_xnt + (size_t)bid * NKC * CHU;

    if (!isW) {
        int tk = tid >> 1, half = tid & 1;
        const float4* xr = reinterpret_cast<const float4*>(src + (size_t)tk * DD + half * (DD / 2));
        float s = 0.f, ss = 0.f;
#pragma unroll 4
        for (int i = 0; i < DD / 8; i++) {
            float4 v = xr[i];
            s  += v.x + v.y + v.z + v.w;
            ss += v.x * v.x + v.y * v.y + v.z * v.z + v.w * v.w;
        }
        s  += __shfl_xor_sync(0xFFFFFFFFu, s, 1);
        ss += __shfl_xor_sync(0xFFFFFFFFu, ss, 1);
        if (!half) {
            float mu = s * (1.0f / DD);
            float var = ss * (1.0f / DD) - mu * mu;
            s_mu[tk] = mu; s_rstd[tk] = rsqrtf(var + EPS);
        }
    }
    __syncthreads();

    for (int kc = 0; kc < NKC; kc++) {
#pragma unroll
        for (int i = 0; i < 4; i++) {
            int id = i * 256 + tid;
            int row = id >> 3, c4 = id & 7;
            float4 v = *reinterpret_cast<const float4*>(src + (size_t)row * DD + kc * 32 + c4 * 4);
            *reinterpret_cast<float4*>(s_t + row * 36 + c4 * 4) = v;
        }
        __syncthreads();
        if (isW) {
#pragma unroll
            for (int j = 0; j < 8; j++) {
                int o = j * 256 + tid;
                int MS = o >> 7, NFP = MS >> 1, ks = MS & 1;
                int lane = (o >> 2) & 31, g = lane >> 2, t = lane & 3, jj = o & 3;
                int n  = NFP * 16 + (jj >> 1) * 8 + g;
                int k0 = ks * 16 + (jj & 1) * 8 + 2 * t;
                dst[(size_t)kc * CHU + o] = pack_h2(s_t[n * 36 + k0], s_t[n * 36 + k0 + 1]);
            }
        } else {
#pragma unroll
            for (int j = 0; j < 8; j++) {
                int o = j * 256 + tid;
                int MS = o >> 7, MF = MS >> 1, ks = MS & 1;
                int lane = (o >> 2) & 31, g = lane >> 2, t = lane & 3, r = o & 3;
                int m  = MF * 16 + (r & 1) * 8 + g;
                int k0 = ks * 16 + (r >> 1) * 8 + 2 * t;
                int kg = kc * 32 + k0;
                float v0 = fmaf((s_t[m * 36 + k0]     - s_mu[m]) * s_rstd[m], gamma[kg],     beta[kg]);
                float v1 = fmaf((s_t[m * 36 + k0 + 1] - s_mu[m]) * s_rstd[m], gamma[kg + 1], beta[kg + 1]);
                dst[(size_t)kc * CHU + o] = pack_h2(v0, v1);
            }
        }
        __syncthreads();
    }
}

// ---------------- kernel 2: fp16 mma.sync GEMM (8 warps, 64x64 tiles, CTA 128x256) ----
__global__ void __launch_bounds__(256, 1)
mamba_mma(const float* __restrict__ x,   const float* __restrict__ bp,
          const float* __restrict__ Wst, const float* __restrict__ bst,
          const float* __restrict__ Wo,  const float* __restrict__ bo,
          const float* __restrict__ istate, float* __restrict__ out)
{
    extern __shared__ uint32_t smu[];
    float* s_su = reinterpret_cast<float*>(smu + STG * STAGE_U32);   // [128][8]
    const int tid = threadIdx.x, lane = tid & 31, wid = tid >> 5;
    const int wm = wid >> 2, wn = wid & 3;   // 2x4 warp grid, 64x64 per warp
    const int tb = blockIdx.x;
    const uint32_t sb = smem_u32(smu);
    const int g = lane >> 2, t = lane & 3;

    for (int i = tid; i < 1024; i += 256) s_su[i] = 0.f;

    const uint32_t* Ab = g_xnt + (size_t)tb * NKC * CHU;

    auto stage = [&](int c) {
        int st = c % 3, et = c >> 5, kc = c & 31;
        const uint32_t* As = Ab + (size_t)kc * CHU;
        const uint32_t* B0 = g_wpt + ((size_t)(et * 2) * NKC + kc) * CHU;
        const uint32_t* B1 = g_wpt + ((size_t)(et * 2 + 1) * NKC + kc) * CHU;
        uint32_t d = sb + st * (STAGE_U32 * 4);
#pragma unroll
        for (int i = 0; i < 2; i++) {
            int id = i * 256 + tid;        // 512 float4 per tensor
            CP_ASYNC16(d + id * 16, As + id * 4);
            CP_ASYNC16(d + 8192 + id * 16, B0 + id * 4);
            CP_ASYNC16(d + 16384 + id * 16, B1 + id * 4);
        }
        CP_COMMIT();
    };
    stage(0); stage(1);

    float acc[4][8][4];
#pragma unroll
    for (int mf = 0; mf < 4; mf++)
#pragma unroll
        for (int nf = 0; nf < 8; nf++)
#pragma unroll
            for (int r = 0; r < 4; r++) acc[mf][nf][r] = 0.f;

    const int aoff = wm * 1024 + lane * 4;                 // (wm*4+mf)*2+ks)*128 base
    const int bsel = (wn >> 1) * 2048 + lane * 4;          // B chunk select
    const int nfp0 = (wn & 1) * 4;                         // warp's first NFP in chunk

    for (int c = 0; c < NCH; c++) {
        CP_WAIT(1);
        __syncthreads();
        if (c + 2 < NCH) stage(c + 2);

        const uint32_t* As = smu + (c % 3) * STAGE_U32;
        const uint32_t* Bs = As + 2048 + bsel;
#pragma unroll
        for (int ks = 0; ks < 2; ks++) {
            uint32_t a[4][4], b[4][4];
#pragma unroll
            for (int mf = 0; mf < 4; mf++) {
                uint4 v = *reinterpret_cast<const uint4*>(As + aoff + (mf * 2 + ks) * 128);
                a[mf][0] = v.x; a[mf][1] = v.y; a[mf][2] = v.z; a[mf][3] = v.w;
            }
#pragma unroll
            for (int p = 0; p < 4; p++) {
                uint4 v = *reinterpret_cast<const uint4*>(Bs + ((nfp0 + p) * 2 + ks) * 128);
                b[p][0] = v.x; b[p][1] = v.y; b[p][2] = v.z; b[p][3] = v.w;
            }
#pragma unroll
            for (int mf = 0; mf < 4; mf++)
#pragma unroll
                for (int p = 0; p < 4; p++) {
                    mma_f16(acc[mf][p * 2],     a[mf], b[p][0], b[p][1]);
                    mma_f16(acc[mf][p * 2 + 1], a[mf], b[p][2], b[p][3]);
                }
        }

        if ((c & 31) == 31) {
            const int et = c >> 5;
#pragma unroll
            for (int mf = 0; mf < 4; mf++) {
                float pr0[8], pr1[8];
#pragma unroll
                for (int n = 0; n < 8; n++) { pr0[n] = 0.f; pr1[n] = 0.f; }
#pragma unroll
                for (int nf = 0; nf < 8; nf++) {
                    int col0 = et * 256 + wn * 64 + nf * 8 + 2 * t;
                    float bp0 = bp[col0], bp1 = bp[col0 + 1];
                    float s00 = silu_f(acc[mf][nf][0] + bp0);
                    float s01 = silu_f(acc[mf][nf][1] + bp1);
                    float s10 = silu_f(acc[mf][nf][2] + bp0);
                    float s11 = silu_f(acc[mf][nf][3] + bp1);
#pragma unroll
                    for (int n = 0; n < 8; n++) {
                        float w0 = Wst[n * EE + col0], w1 = Wst[n * EE + col0 + 1];
                        pr0[n] = fmaf(s00, w0, fmaf(s01, w1, pr0[n]));
                        pr1[n] = fmaf(s10, w0, fmaf(s11, w1, pr1[n]));
                    }
                }
#pragma unroll
                for (int n = 0; n < 8; n++) {
                    pr0[n] += __shfl_xor_sync(0xFFFFFFFFu, pr0[n], 1);
                    pr0[n] += __shfl_xor_sync(0xFFFFFFFFu, pr0[n], 2);
                    pr1[n] += __shfl_xor_sync(0xFFFFFFFFu, pr1[n], 1);
                    pr1[n] += __shfl_xor_sync(0xFFFFFFFFu, pr1[n], 2);
                }
                if (t == 0) {
                    int r0 = wm * 64 + mf * 16 + g;
#pragma unroll
                    for (int n = 0; n < 8; n++) {
                        atomicAdd(&s_su[r0 * 8 + n], pr0[n]);
                        atomicAdd(&s_su[(r0 + 8) * 8 + n], pr1[n]);
                    }
                }
            }
#pragma unroll
            for (int mf = 0; mf < 4; mf++)
#pragma unroll
                for (int nf = 0; nf < 8; nf++)
#pragma unroll
                    for (int r = 0; r < 4; r++) acc[mf][nf][r] = 0.f;
        }
    }
    __syncthreads();

    // current_state = silu(init + b_state + su)
    for (int i = tid; i < 1024; i += 256) {
        int n = i & 7;
        s_su[i] = silu_f(s_su[i] + bst[n] + istate[n]);
    }
    __syncthreads();

    // tail: out = x + cs @ WoT + bo
    const float4* x4 = reinterpret_cast<const float4*>(x + (size_t)tb * 128 * DD);
    float4*       o4 = reinterpret_cast<float4*>(out + (size_t)tb * 128 * DD);
    for (int idx = tid; idx < 128 * (DD / 4); idx += 256) {
        int tt = idx >> 8, cc = idx & 255;
        float4 xv  = x4[idx];
        float4 cs0 = *reinterpret_cast<const float4*>(s_su + tt * NS);
        float4 cs1 = *reinterpret_cast<const float4*>(s_su + tt * NS + 4);
        float xin[4] = {xv.x, xv.y, xv.z, xv.w};
        float ov[4];
        int d0 = cc * 4;
#pragma unroll
        for (int dd = 0; dd < 4; dd++) {
            int d = d0 + dd;
            const float4* wo = reinterpret_cast<const float4*>(Wo + (size_t)d * NS);
            float4 w0 = wo[0], w1 = wo[1];
            float o = bo[d];
            o = fmaf(cs0.x, w0.x, o); o = fmaf(cs0.y, w0.y, o);
            o = fmaf(cs0.z, w0.z, o); o = fmaf(cs0.w, w0.w, o);
            o = fmaf(cs1.x, w1.x, o); o = fmaf(cs1.y, w1.y, o);
            o = fmaf(cs1.z, w1.z, o); o = fmaf(cs1.w, w1.w, o);
            ov[dd] = xin[dd] + o;
        }
        o4[idx] = make_float4(ov[0], ov[1], ov[2], ov[3]);
    }
}

extern "C" void kernel_launch(void* const* d_in, const int* in_sizes, int n_in,
                              void* d_out, int out_size) {
    (void)in_sizes; (void)n_in; (void)out_size;
    const float* x      = (const float*)d_in[0];
    const float* Wp     = (const float*)d_in[1];
    const float* bp     = (const float*)d_in[2];
    const float* Wst    = (const float*)d_in[3];
    const float* bst    = (const float*)d_in[4];
    const float* Wo     = (const float*)d_in[5];
    const float* bo     = (const float*)d_in[6];
    const float* istate = (const float*)d_in[7];
    const float* gamma  = (const float*)d_in[8];
    const float* beta   = (const float*)d_in[9];

    prep<<<NBLK + NET, 256>>>(x, Wp, gamma, beta);

    cudaFuncSetAttribute(mamba_mma,
                         cudaFuncAttributeMaxDynamicSharedMemorySize, SMEM_BYTES);
    mamba_mma<<<NBLK, 256, SMEM_BYTES>>>(x, bp, Wst, bst, Wo, bo, istate, (float*)d_out);
}

// round 10
// speedup vs baseline: 1.5439x; 1.0838x over previous
#include <cuda_runtime.h>
#include <cuda_fp16.h>
#include <cstdint>

// ---------------- problem constants ----------------
#define TT 50176
#define DD 1024
#define EE 2048
#define NS 8
#define EPS 1e-5f

#define NBLK 392            // token blocks of 128
#define NET 16              // packed e chunks of 128 cols
#define NKC 32              // packed K chunks of 32
#define CHU 2048            // u32 (half2) per packed 128x32 chunk
#define NCH 256             // 16 et-passes x 16 K-steps of 64
#define STG 3
#define STAGE_U32 8192      // A 2x2048 + B 2x2048
#define SMEM_BYTES (STG * STAGE_U32 * 4 + 4096)   // 102400

// ---------------- scratch (device globals; no allocation) ----------------
__device__ uint32_t g_xnt[(size_t)NBLK * NKC * CHU];  // frag-packed xn (fp16)
__device__ uint32_t g_wpt[(size_t)NET * NKC * CHU];   // frag-packed Wp (fp16)

// ---------------- helpers ----------------
__device__ __forceinline__ float silu_f(float v) { return v * (1.0f / (1.0f + __expf(-v))); }
__device__ __forceinline__ uint32_t smem_u32(const void* p) {
    uint32_t a;
    asm("{ .reg .u64 t; cvta.to.shared.u64 t, %1; cvt.u32.u64 %0, t; }" : "=r"(a) : "l"(p));
    return a;
}
__device__ __forceinline__ uint32_t pack_h2(float lo, float hi) {
    __half2 h = __halves2half2(__float2half_rn(lo), __float2half_rn(hi));
    return *reinterpret_cast<uint32_t*>(&h);
}
#define CP_ASYNC16(dst, src) \
    asm volatile("cp.async.cg.shared.global [%0], [%1], 16;" :: "r"(dst), "l"(src))
#define CP_COMMIT() asm volatile("cp.async.commit_group;")
#define CP_WAIT(n)  asm volatile("cp.async.wait_group %0;" :: "n"(n))

__device__ __forceinline__ void mma_f16(float d[4], const uint32_t a[4],
                                        uint32_t b0, uint32_t b1) {
    asm volatile(
        "mma.sync.aligned.m16n8k16.row.col.f32.f16.f16.f32 "
        "{%0,%1,%2,%3}, {%4,%5,%6,%7}, {%8,%9}, {%0,%1,%2,%3};"
        : "+f"(d[0]), "+f"(d[1]), "+f"(d[2]), "+f"(d[3])
        : "r"(a[0]), "r"(a[1]), "r"(a[2]), "r"(a[3]), "r"(b0), "r"(b1));
}

// ---------------- kernel 1: LN + fp16 round + fragment packing (K32 chunks) ----------
__global__ void __launch_bounds__(256)
prep(const float* __restrict__ x, const float* __restrict__ Wp,
     const float* __restrict__ gamma, const float* __restrict__ beta)
{
    __shared__ float s_mu[128], s_rstd[128];
    __shared__ float s_t[128 * 36];
    const int bid = blockIdx.x, tid = threadIdx.x;
    const bool isW = (bid >= NBLK);
    const float* src = isW ? Wp + (size_t)(bid - NBLK) * 128 * DD
                           : x + (size_t)bid * 128 * DD;
    uint32_t* dst = isW ? g_wpt + (size_t)(bid - NBLK) * NKC * CHU
                        : g_xnt + (size_t)bid * NKC * CHU;

    if (!isW) {
        int tk = tid >> 1, half = tid & 1;
        const float4* xr = reinterpret_cast<const float4*>(src + (size_t)tk * DD + half * (DD / 2));
        float s = 0.f, ss = 0.f;
#pragma unroll 4
        for (int i = 0; i < DD / 8; i++) {
            float4 v = xr[i];
            s  += v.x + v.y + v.z + v.w;
            ss += v.x * v.x + v.y * v.y + v.z * v.z + v.w * v.w;
        }
        s  += __shfl_xor_sync(0xFFFFFFFFu, s, 1);
        ss += __shfl_xor_sync(0xFFFFFFFFu, ss, 1);
        if (!half) {
            float mu = s * (1.0f / DD);
            float var = ss * (1.0f / DD) - mu * mu;
            s_mu[tk] = mu; s_rstd[tk] = rsqrtf(var + EPS);
        }
    }
    __syncthreads();

    for (int kc = 0; kc < NKC; kc++) {
#pragma unroll
        for (int i = 0; i < 4; i++) {
            int id = i * 256 + tid;
            int row = id >> 3, c4 = id & 7;
            float4 v = *reinterpret_cast<const float4*>(src + (size_t)row * DD + kc * 32 + c4 * 4);
            *reinterpret_cast<float4*>(s_t + row * 36 + c4 * 4) = v;
        }
        __syncthreads();
        if (isW) {
#pragma unroll
            for (int j = 0; j < 8; j++) {
                int o = j * 256 + tid;
                int MS = o >> 7, NFP = MS >> 1, ks = MS & 1;
                int lane = (o >> 2) & 31, g = lane >> 2, t = lane & 3, jj = o & 3;
                int n  = NFP * 16 + (jj >> 1) * 8 + g;
                int k0 = ks * 16 + (jj & 1) * 8 + 2 * t;
                dst[(size_t)kc * CHU + o] = pack_h2(s_t[n * 36 + k0], s_t[n * 36 + k0 + 1]);
            }
        } else {
#pragma unroll
            for (int j = 0; j < 8; j++) {
                int o = j * 256 + tid;
                int MS = o >> 7, MF = MS >> 1, ks = MS & 1;
                int lane = (o >> 2) & 31, g = lane >> 2, t = lane & 3, r = o & 3;
                int m  = MF * 16 + (r & 1) * 8 + g;
                int k0 = ks * 16 + (r >> 1) * 8 + 2 * t;
                int kg = kc * 32 + k0;
                float v0 = fmaf((s_t[m * 36 + k0]     - s_mu[m]) * s_rstd[m], gamma[kg],     beta[kg]);
                float v1 = fmaf((s_t[m * 36 + k0 + 1] - s_mu[m]) * s_rstd[m], gamma[kg + 1], beta[kg + 1]);
                dst[(size_t)kc * CHU + o] = pack_h2(v0, v1);
            }
        }
        __syncthreads();
    }
}

// ---------------- kernel 2: fp16 mma.sync (8 warps, 64x32 tiles, 2 CTA/SM, BK=64) ----
__global__ void __launch_bounds__(256, 2)
mamba_mma(const float* __restrict__ x,   const float* __restrict__ bp,
          const float* __restrict__ Wst, const float* __restrict__ bst,
          const float* __restrict__ Wo,  const float* __restrict__ bo,
          const float* __restrict__ istate, float* __restrict__ out)
{
    extern __shared__ uint32_t smu[];
    float* s_su = reinterpret_cast<float*>(smu + STG * STAGE_U32);   // [128][8]
    const int tid = threadIdx.x, lane = tid & 31, wid = tid >> 5;
    const int wm = wid >> 2, wn = wid & 3;   // 2x4 warp grid, 64x32 per warp
    const int tb = blockIdx.x;
    const uint32_t sb = smem_u32(smu);
    const int g = lane >> 2, t = lane & 3;

    for (int i = tid; i < 1024; i += 256) s_su[i] = 0.f;

    const uint32_t* Ab = g_xnt + (size_t)tb * NKC * CHU;

    auto stage = [&](int c) {
        int st = c % 3, et = c >> 4, k2 = c & 15;
        const uint32_t* As = Ab + (size_t)(k2 * 2) * CHU;                    // 2 kc chunks
        const uint32_t* Bs = g_wpt + ((size_t)et * NKC + k2 * 2) * CHU;
        uint32_t d = sb + st * (STAGE_U32 * 4);
#pragma unroll
        for (int i = 0; i < 4; i++) {
            int id = i * 256 + tid;        // 1024 uint4 per tensor pair (2 chunks)
            CP_ASYNC16(d + id * 16, As + id * 4);
            CP_ASYNC16(d + 16384 + id * 16, Bs + id * 4);
        }
        CP_COMMIT();
    };
    stage(0); stage(1);

    float acc[4][4][4];
#pragma unroll
    for (int mf = 0; mf < 4; mf++)
#pragma unroll
        for (int nf = 0; nf < 4; nf++)
#pragma unroll
            for (int r = 0; r < 4; r++) acc[mf][nf][r] = 0.f;

    const int aoff = wm * 1024 + lane * 4;       // + ksub*2048 + (mf*2+ks)*128
    const int boff = 4096 + wn * 512 + lane * 4; // FIX: NFP=wn*2+p, 512 u32 per warp (2 NFPs)

    for (int c = 0; c < NCH; c++) {
        CP_WAIT(1);
        __syncthreads();
        if (c + 2 < NCH) stage(c + 2);

        const uint32_t* St = smu + (c % 3) * STAGE_U32;
#pragma unroll
        for (int ksg = 0; ksg < 4; ksg++) {
            const int ksub = ksg >> 1, ks = ksg & 1;
            const uint32_t* As = St + ksub * 2048 + aoff + ks * 128;
            const uint32_t* Bs = St + ksub * 2048 + boff + ks * 128;
            uint32_t a[4][4], b[2][4];
#pragma unroll
            for (int mf = 0; mf < 4; mf++) {
                uint4 v = *reinterpret_cast<const uint4*>(As + mf * 256);
                a[mf][0] = v.x; a[mf][1] = v.y; a[mf][2] = v.z; a[mf][3] = v.w;
            }
#pragma unroll
            for (int p = 0; p < 2; p++) {
                uint4 v = *reinterpret_cast<const uint4*>(Bs + p * 256);
                b[p][0] = v.x; b[p][1] = v.y; b[p][2] = v.z; b[p][3] = v.w;
            }
#pragma unroll
            for (int mf = 0; mf < 4; mf++)
#pragma unroll
                for (int p = 0; p < 2; p++) {
                    mma_f16(acc[mf][p * 2],     a[mf], b[p][0], b[p][1]);
                    mma_f16(acc[mf][p * 2 + 1], a[mf], b[p][2], b[p][3]);
                }
        }

        if ((c & 15) == 15) {
            const int et = c >> 4;
#pragma unroll
            for (int mf = 0; mf < 4; mf++) {
                float pr0[8], pr1[8];
#pragma unroll
                for (int n = 0; n < 8; n++) { pr0[n] = 0.f; pr1[n] = 0.f; }
#pragma unroll
                for (int nf = 0; nf < 4; nf++) {
                    int col0 = et * 128 + wn * 32 + nf * 8 + 2 * t;
                    float bp0 = bp[col0], bp1 = bp[col0 + 1];
                    float s00 = silu_f(acc[mf][nf][0] + bp0);
                    float s01 = silu_f(acc[mf][nf][1] + bp1);
                    float s10 = silu_f(acc[mf][nf][2] + bp0);
                    float s11 = silu_f(acc[mf][nf][3] + bp1);
#pragma unroll
                    for (int n = 0; n < 8; n++) {
                        float w0 = Wst[n * EE + col0], w1 = Wst[n * EE + col0 + 1];
                        pr0[n] = fmaf(s00, w0, fmaf(s01, w1, pr0[n]));
                        pr1[n] = fmaf(s10, w0, fmaf(s11, w1, pr1[n]));
                    }
                }
#pragma unroll
                for (int n = 0; n < 8; n++) {
                    pr0[n] += __shfl_xor_sync(0xFFFFFFFFu, pr0[n], 1);
                    pr0[n] += __shfl_xor_sync(0xFFFFFFFFu, pr0[n], 2);
                    pr1[n] += __shfl_xor_sync(0xFFFFFFFFu, pr1[n], 1);
                    pr1[n] += __shfl_xor_sync(0xFFFFFFFFu, pr1[n], 2);
                }
                if (t == 0) {
                    int r0 = wm * 64 + mf * 16 + g;
#pragma unroll
                    for (int n = 0; n < 8; n++) {
                        atomicAdd(&s_su[r0 * 8 + n], pr0[n]);
                        atomicAdd(&s_su[(r0 + 8) * 8 + n], pr1[n]);
                    }
                }
            }
#pragma unroll
            for (int mf = 0; mf < 4; mf++)
#pragma unroll
                for (int nf = 0; nf < 4; nf++)
#pragma unroll
                    for (int r = 0; r < 4; r++) acc[mf][nf][r] = 0.f;
        }
    }
    __syncthreads();

    // current_state = silu(init + b_state + su)
    for (int i = tid; i < 1024; i += 256) {
        int n = i & 7;
        s_su[i] = silu_f(s_su[i] + bst[n] + istate[n]);
    }
    __syncthreads();

    // tail: out = x + cs @ WoT + bo
    const float4* x4 = reinterpret_cast<const float4*>(x + (size_t)tb * 128 * DD);
    float4*       o4 = reinterpret_cast<float4*>(out + (size_t)tb * 128 * DD);
    for (int idx = tid; idx < 128 * (DD / 4); idx += 256) {
        int tt = idx >> 8, cc = idx & 255;
        float4 xv  = x4[idx];
        float4 cs0 = *reinterpret_cast<const float4*>(s_su + tt * NS);
        float4 cs1 = *reinterpret_cast<const float4*>(s_su + tt * NS + 4);
        float xin[4] = {xv.x, xv.y, xv.z, xv.w};
        float ov[4];
        int d0 = cc * 4;
#pragma unroll
        for (int dd = 0; dd < 4; dd++) {
            int d = d0 + dd;
            const float4* wo = reinterpret_cast<const float4*>(Wo + (size_t)d * NS);
            float4 w0 = wo[0], w1 = wo[1];
            float o = bo[d];
            o = fmaf(cs0.x, w0.x, o); o = fmaf(cs0.y, w0.y, o);
            o = fmaf(cs0.z, w0.z, o); o = fmaf(cs0.w, w0.w, o);
            o = fmaf(cs1.x, w1.x, o); o = fmaf(cs1.y, w1.y, o);
            o = fmaf(cs1.z, w1.z, o); o = fmaf(cs1.w, w1.w, o);
            ov[dd] = xin[dd] + o;
        }
        o4[idx] = make_float4(ov[0], ov[1], ov[2], ov[3]);
    }
}

extern "C" void kernel_launch(void* const* d_in, const int* in_sizes, int n_in,
                              void* d_out, int out_size) {
    (void)in_sizes; (void)n_in; (void)out_size;
    const float* x      = (const float*)d_in[0];
    const float* Wp     = (const float*)d_in[1];
    const float* bp     = (const float*)d_in[2];
    const float* Wst    = (const float*)d_in[3];
    const float* bst    = (const float*)d_in[4];
    const float* Wo     = (const float*)d_in[5];
    const float* bo     = (const float*)d_in[6];
    const float* istate = (const float*)d_in[7];
    const float* gamma  = (const float*)d_in[8];
    const float* beta   = (const float*)d_in[9];

    prep<<<NBLK + NET, 256>>>(x, Wp, gamma, beta);

    cudaFuncSetAttribute(mamba_mma,
                         cudaFuncAttributeMaxDynamicSharedMemorySize, SMEM_BYTES);
    mamba_mma<<<NBLK, 256, SMEM_BYTES>>>(x, bp, Wst, bst, Wo, bo, istate, (float*)d_out);
}

// round 11
// speedup vs baseline: 1.6609x; 1.0758x over previous
#include <cuda_runtime.h>
#include <cuda_fp16.h>
#include <cstdint>

// ---------------- problem constants ----------------
#define TT 50176
#define DD 1024
#define EE 2048
#define NS 8
#define EPS 1e-5f

#define NBLK 392            // token blocks of 128
#define NET 16              // packed e chunks of 128 cols
#define NKC 32              // packed K chunks of 32
#define CHU 2048            // u32 (half2) per packed 128x32 chunk
#define NCH 256             // 16 et-passes x 16 K-steps of 64
#define STG 3
#define STAGE_U32 8192      // A 2x2048 + B 2x2048 per stage (32 KB)
#define SU_BYTE   (STG * STAGE_U32 * 4)        // 98304
#define MBAR_BYTE (SU_BYTE + 4096)             // 102400
#define SMEM_BYTES (MBAR_BYTE + 64)            // 102464

// ---------------- scratch (device globals; no allocation) ----------------
__device__ uint32_t g_xnt[(size_t)NBLK * NKC * CHU];  // frag-packed xn (fp16)
__device__ uint32_t g_wpt[(size_t)NET * NKC * CHU];   // frag-packed Wp (fp16)

// ---------------- helpers ----------------
__device__ __forceinline__ float silu_f(float v) { return v * (1.0f / (1.0f + __expf(-v))); }
__device__ __forceinline__ uint32_t smem_u32(const void* p) {
    uint32_t a;
    asm("{ .reg .u64 t; cvta.to.shared.u64 t, %1; cvt.u32.u64 %0, t; }" : "=r"(a) : "l"(p));
    return a;
}
__device__ __forceinline__ uint32_t pack_h2(float lo, float hi) {
    __half2 h = __halves2half2(__float2half_rn(lo), __float2half_rn(hi));
    return *reinterpret_cast<uint32_t*>(&h);
}
#define CP_ASYNC16(dst, src) \
    asm volatile("cp.async.cg.shared.global [%0], [%1], 16;" :: "r"(dst), "l"(src))
#define CPA_MBAR_ARRIVE(addr) \
    asm volatile("cp.async.mbarrier.arrive.noinc.shared.b64 [%0];" :: "r"(addr) : "memory")
#define MBARRIER_INIT(addr, cnt) \
    asm volatile("mbarrier.init.shared.b64 [%0], %1;" :: "r"(addr), "r"(cnt) : "memory")
#define MBAR_ARRIVE(addr) \
    asm volatile("mbarrier.arrive.shared.b64 _, [%0];" :: "r"(addr) : "memory")

#define MBARRIER_WAIT(addr, ph) do {                                            \
    uint32_t _m = (addr), _p = (uint32_t)(ph), _d;                              \
    asm volatile("{ .reg .pred p; mbarrier.try_wait.parity.acquire.cta.shared::cta.b64 p, [%1], %2; selp.b32 %0,1,0,p; }" \
        : "=r"(_d) : "r"(_m), "r"(_p) : "memory");                              \
    if (!_d) { asm volatile(                                                    \
        "{ .reg .pred P; WL%=: mbarrier.try_wait.parity.acquire.cta.shared::cta.b64 P, [%0], %1, 0x989680;" \
        " @P bra.uni WD%=; bra.uni WL%=; WD%=: }" :: "r"(_m), "r"(_p) : "memory"); } \
} while (0)

#define MBARRIER_WAIT_RELAXED(addr, ph) do {                                    \
    uint32_t _m = (addr), _p = (uint32_t)(ph), _d;                              \
    asm volatile("{ .reg .pred p; mbarrier.try_wait.parity.relaxed.cta.shared::cta.b64 p, [%1], %2, 0x989680; selp.b32 %0,1,0,p; }" \
        : "=r"(_d) : "r"(_m), "r"(_p) : "memory");                              \
    if (!_d) { asm volatile(                                                    \
        "{ .reg .pred P; WL%=: mbarrier.try_wait.parity.relaxed.cta.shared::cta.b64 P, [%0], %1, 0x989680;" \
        " @P bra.uni WD%=; bra.uni WL%=; WD%=: }" :: "r"(_m), "r"(_p) : "memory"); } \
} while (0)

__device__ __forceinline__ void mma_f16(float d[4], const uint32_t a[4],
                                        uint32_t b0, uint32_t b1) {
    asm volatile(
        "mma.sync.aligned.m16n8k16.row.col.f32.f16.f16.f32 "
        "{%0,%1,%2,%3}, {%4,%5,%6,%7}, {%8,%9}, {%0,%1,%2,%3};"
        : "+f"(d[0]), "+f"(d[1]), "+f"(d[2]), "+f"(d[3])
        : "r"(a[0]), "r"(a[1]), "r"(a[2]), "r"(a[3]), "r"(b0), "r"(b1));
}

// ---------------- kernel 1: LN + fp16 round + fragment packing (K32 chunks) ----------
__global__ void __launch_bounds__(256)
prep(const float* __restrict__ x, const float* __restrict__ Wp,
     const float* __restrict__ gamma, const float* __restrict__ beta)
{
    __shared__ float s_mu[128], s_rstd[128];
    __shared__ float s_t[128 * 36];
    const int bid = blockIdx.x, tid = threadIdx.x;
    const bool isW = (bid >= NBLK);
    const float* src = isW ? Wp + (size_t)(bid - NBLK) * 128 * DD
                           : x + (size_t)bid * 128 * DD;
    uint32_t* dst = isW ? g_wpt + (size_t)(bid - NBLK) * NKC * CHU
                        : g_xnt + (size_t)bid * NKC * CHU;

    if (!isW) {
        int tk = tid >> 1, half = tid & 1;
        const float4* xr = reinterpret_cast<const float4*>(src + (size_t)tk * DD + half * (DD / 2));
        float s = 0.f, ss = 0.f;
#pragma unroll 4
        for (int i = 0; i < DD / 8; i++) {
            float4 v = xr[i];
            s  += v.x + v.y + v.z + v.w;
            ss += v.x * v.x + v.y * v.y + v.z * v.z + v.w * v.w;
        }
        s  += __shfl_xor_sync(0xFFFFFFFFu, s, 1);
        ss += __shfl_xor_sync(0xFFFFFFFFu, ss, 1);
        if (!half) {
            float mu = s * (1.0f / DD);
            float var = ss * (1.0f / DD) - mu * mu;
            s_mu[tk] = mu; s_rstd[tk] = rsqrtf(var + EPS);
        }
    }
    __syncthreads();

    for (int kc = 0; kc < NKC; kc++) {
#pragma unroll
        for (int i = 0; i < 4; i++) {
            int id = i * 256 + tid;
            int row = id >> 3, c4 = id & 7;
            float4 v = *reinterpret_cast<const float4*>(src + (size_t)row * DD + kc * 32 + c4 * 4);
            *reinterpret_cast<float4*>(s_t + row * 36 + c4 * 4) = v;
        }
        __syncthreads();
        if (isW) {
#pragma unroll
            for (int j = 0; j < 8; j++) {
                int o = j * 256 + tid;
                int MS = o >> 7, NFP = MS >> 1, ks = MS & 1;
                int lane = (o >> 2) & 31, g = lane >> 2, t = lane & 3, jj = o & 3;
                int n  = NFP * 16 + (jj >> 1) * 8 + g;
                int k0 = ks * 16 + (jj & 1) * 8 + 2 * t;
                dst[(size_t)kc * CHU + o] = pack_h2(s_t[n * 36 + k0], s_t[n * 36 + k0 + 1]);
            }
        } else {
#pragma unroll
            for (int j = 0; j < 8; j++) {
                int o = j * 256 + tid;
                int MS = o >> 7, MF = MS >> 1, ks = MS & 1;
                int lane = (o >> 2) & 31, g = lane >> 2, t = lane & 3, r = o & 3;
                int m  = MF * 16 + (r & 1) * 8 + g;
                int k0 = ks * 16 + (r >> 1) * 8 + 2 * t;
                int kg = kc * 32 + k0;
                float v0 = fmaf((s_t[m * 36 + k0]     - s_mu[m]) * s_rstd[m], gamma[kg],     beta[kg]);
                float v1 = fmaf((s_t[m * 36 + k0 + 1] - s_mu[m]) * s_rstd[m], gamma[kg + 1], beta[kg + 1]);
                dst[(size_t)kc * CHU + o] = pack_h2(v0, v1);
            }
        }
        __syncthreads();
    }
}

// ---- kernel 2: fp16 mma.sync, 8 warps 64x32, 2 CTA/SM, mbarrier ring (no CTA barrier) ----
__global__ void __launch_bounds__(256, 2)
mamba_mma(const float* __restrict__ x,   const float* __restrict__ bp,
          const float* __restrict__ Wst, const float* __restrict__ bst,
          const float* __restrict__ Wo,  const float* __restrict__ bo,
          const float* __restrict__ istate, float* __restrict__ out)
{
    extern __shared__ uint32_t smu[];
    float* s_su = reinterpret_cast<float*>(reinterpret_cast<char*>(smu) + SU_BYTE); // [128][8]
    const int tid = threadIdx.x, lane = tid & 31, wid = tid >> 5;
    const int wm = wid >> 2, wn = wid & 3;   // 2x4 warp grid, 64x32 per warp
    const int tb = blockIdx.x;
    const uint32_t sb = smem_u32(smu);
    const uint32_t mb_full = sb + MBAR_BYTE;       // 3 x 8B
    const uint32_t mb_free = sb + MBAR_BYTE + 24;  // 3 x 8B
    const int g = lane >> 2, t = lane & 3;

    for (int i = tid; i < 1024; i += 256) s_su[i] = 0.f;
    if (tid == 0) {
#pragma unroll
        for (int s = 0; s < STG; s++) {
            MBARRIER_INIT(mb_full + 8 * s, 256);
            MBARRIER_INIT(mb_free + 8 * s, 256);
        }
    }
    __syncthreads();

    const uint32_t* Ab = g_xnt + (size_t)tb * NKC * CHU;

    // stage loader: wait free[st], issue this thread's cp.asyncs, signal full[st]
    auto stage_load = [&](int cc) {
        int st = cc % 3, m = cc / 3;
        MBARRIER_WAIT_RELAXED(mb_free + 8 * st, (m + 1) & 1);   // m=0 passes immediately
        int et = cc >> 4, k2 = cc & 15;
        const uint32_t* As = Ab + (size_t)(k2 * 2) * CHU;
        const uint32_t* Bs = g_wpt + ((size_t)et * NKC + k2 * 2) * CHU;
        uint32_t d = sb + st * (STAGE_U32 * 4);
#pragma unroll
        for (int i = 0; i < 4; i++) {
            int id = i * 256 + tid;
            CP_ASYNC16(d + id * 16, As + id * 4);
            CP_ASYNC16(d + 16384 + id * 16, Bs + id * 4);
        }
        CPA_MBAR_ARRIVE(mb_full + 8 * st);
    };
    stage_load(0); stage_load(1);

    float acc[4][4][4];
#pragma unroll
    for (int mf = 0; mf < 4; mf++)
#pragma unroll
        for (int nf = 0; nf < 4; nf++)
#pragma unroll
            for (int r = 0; r < 4; r++) acc[mf][nf][r] = 0.f;

    const int aoff = wm * 1024 + lane * 4;       // + ksub*2048 + (mf*2+ks)*128
    const int boff = 4096 + wn * 512 + lane * 4; // NFP = wn*2+p, 512 u32 per warp

    for (int c = 0; c < NCH; c++) {
        if (c + 2 < NCH) stage_load(c + 2);

        const int st = c % 3;
        MBARRIER_WAIT(mb_full + 8 * st, (c / 3) & 1);

        const uint32_t* St = smu + st * STAGE_U32;
#pragma unroll
        for (int ksg = 0; ksg < 4; ksg++) {
            const int ksub = ksg >> 1, ks = ksg & 1;
            const uint32_t* As = St + ksub * 2048 + aoff + ks * 128;
            const uint32_t* Bs = St + ksub * 2048 + boff + ks * 128;
            uint32_t a[4][4], b[2][4];
#pragma unroll
            for (int mf = 0; mf < 4; mf++) {
                uint4 v = *reinterpret_cast<const uint4*>(As + mf * 256);
                a[mf][0] = v.x; a[mf][1] = v.y; a[mf][2] = v.z; a[mf][3] = v.w;
            }
#pragma unroll
            for (int p = 0; p < 2; p++) {
                uint4 v = *reinterpret_cast<const uint4*>(Bs + p * 256);
                b[p][0] = v.x; b[p][1] = v.y; b[p][2] = v.z; b[p][3] = v.w;
            }
#pragma unroll
            for (int mf = 0; mf < 4; mf++)
#pragma unroll
                for (int p = 0; p < 2; p++) {
                    mma_f16(acc[mf][p * 2],     a[mf], b[p][0], b[p][1]);
                    mma_f16(acc[mf][p * 2 + 1], a[mf], b[p][2], b[p][3]);
                }
        }
        MBAR_ARRIVE(mb_free + 8 * st);   // this thread is done reading stage st

        if ((c & 15) == 15) {
            const int et = c >> 4;
#pragma unroll
            for (int mf = 0; mf < 4; mf++) {
                float pr0[8], pr1[8];
#pragma unroll
                for (int n = 0; n < 8; n++) { pr0[n] = 0.f; pr1[n] = 0.f; }
#pragma unroll
                for (int nf = 0; nf < 4; nf++) {
                    int col0 = et * 128 + wn * 32 + nf * 8 + 2 * t;
                    float bp0 = bp[col0], bp1 = bp[col0 + 1];
                    float s00 = silu_f(acc[mf][nf][0] + bp0);
                    float s01 = silu_f(acc[mf][nf][1] + bp1);
                    float s10 = silu_f(acc[mf][nf][2] + bp0);
                    float s11 = silu_f(acc[mf][nf][3] + bp1);
#pragma unroll
                    for (int n = 0; n < 8; n++) {
                        float w0 = Wst[n * EE + col0], w1 = Wst[n * EE + col0 + 1];
                        pr0[n] = fmaf(s00, w0, fmaf(s01, w1, pr0[n]));
                        pr1[n] = fmaf(s10, w0, fmaf(s11, w1, pr1[n]));
                    }
                }
#pragma unroll
                for (int n = 0; n < 8; n++) {
                    pr0[n] += __shfl_xor_sync(0xFFFFFFFFu, pr0[n], 1);
                    pr0[n] += __shfl_xor_sync(0xFFFFFFFFu, pr0[n], 2);
                    pr1[n] += __shfl_xor_sync(0xFFFFFFFFu, pr1[n], 1);
                    pr1[n] += __shfl_xor_sync(0xFFFFFFFFu, pr1[n], 2);
                }
                if (t == 0) {
                    int r0 = wm * 64 + mf * 16 + g;
#pragma unroll
                    for (int n = 0; n < 8; n++) {
                        atomicAdd(&s_su[r0 * 8 + n], pr0[n]);
                        atomicAdd(&s_su[(r0 + 8) * 8 + n], pr1[n]);
                    }
                }
            }
#pragma unroll
            for (int mf = 0; mf < 4; mf++)
#pragma unroll
                for (int nf = 0; nf < 4; nf++)
#pragma unroll
                    for (int r = 0; r < 4; r++) acc[mf][nf][r] = 0.f;
        }
    }
    __syncthreads();

    // current_state = silu(init + b_state + su)
    for (int i = tid; i < 1024; i += 256) {
        int n = i & 7;
        s_su[i] = silu_f(s_su[i] + bst[n] + istate[n]);
    }
    __syncthreads();

    // tail: out = x + cs @ WoT + bo
    const float4* x4 = reinterpret_cast<const float4*>(x + (size_t)tb * 128 * DD);
    float4*       o4 = reinterpret_cast<float4*>(out + (size_t)tb * 128 * DD);
    for (int idx = tid; idx < 128 * (DD / 4); idx += 256) {
        int tt = idx >> 8, cc = idx & 255;
        float4 xv  = x4[idx];
        float4 cs0 = *reinterpret_cast<const float4*>(s_su + tt * NS);
        float4 cs1 = *reinterpret_cast<const float4*>(s_su + tt * NS + 4);
        float xin[4] = {xv.x, xv.y, xv.z, xv.w};
        float ov[4];
        int d0 = cc * 4;
#pragma unroll
        for (int dd = 0; dd < 4; dd++) {
            int d = d0 + dd;
            const float4* wo = reinterpret_cast<const float4*>(Wo + (size_t)d * NS);
            float4 w0 = wo[0], w1 = wo[1];
            float o = bo[d];
            o = fmaf(cs0.x, w0.x, o); o = fmaf(cs0.y, w0.y, o);
            o = fmaf(cs0.z, w0.z, o); o = fmaf(cs0.w, w0.w, o);
            o = fmaf(cs1.x, w1.x, o); o = fmaf(cs1.y, w1.y, o);
            o = fmaf(cs1.z, w1.z, o); o = fmaf(cs1.w, w1.w, o);
            ov[dd] = xin[dd] + o;
        }
        o4[idx] = make_float4(ov[0], ov[1], ov[2], ov[3]);
    }
}

extern "C" void kernel_launch(void* const* d_in, const int* in_sizes, int n_in,
                              void* d_out, int out_size) {
    (void)in_sizes; (void)n_in; (void)out_size;
    const float* x      = (const float*)d_in[0];
    const float* Wp     = (const float*)d_in[1];
    const float* bp     = (const float*)d_in[2];
    const float* Wst    = (const float*)d_in[3];
    const float* bst    = (const float*)d_in[4];
    const float* Wo     = (const float*)d_in[5];
    const float* bo     = (const float*)d_in[6];
    const float* istate = (const float*)d_in[7];
    const float* gamma  = (const float*)d_in[8];
    const float* beta   = (const float*)d_in[9];

    prep<<<NBLK + NET, 256>>>(x, Wp, gamma, beta);

    cudaFuncSetAttribute(mamba_mma,
                         cudaFuncAttributeMaxDynamicSharedMemorySize, SMEM_BYTES);
    mamba_mma<<<NBLK, 256, SMEM_BYTES>>>(x, bp, Wst, bst, Wo, bo, istate, (float*)d_out);
}